// round 9
// baseline (speedup 1.0000x reference)
#include <cuda_runtime.h>
#include <cuda_bf16.h>
#include <mma.h>
#include <math.h>
#include <cstdint>

using namespace nvcuda;

// Problem constants (fixed by the dataset)
#define BATCH 8
#define SEQ   2048
#define HDIM  4096
#define DDIM  128
#define NSENT 128

// split-K for the HMMA GEMM
#define KS2   16
#define KSL   (HDIM / KS2)     // 256 fp32 k per CTA
#define STG   64               // k per pipeline stage
#define NSTG  (KSL / STG)      // 4 stages

#define TSTRIDE 72             // bf16 tile row stride (144B, 16B-aligned, conflict-free)
#define ATILE   (128 * TSTRIDE * 2)   // 18432 bytes per bf16 tile
#define RAWA_SZ (128 * STG * 4)       // 32768 bytes raw fp32 A stage
#define AT_OFF  (2 * RAWA_SZ)         // 65536 : A hi/lo tiles (single buffered)
#define WT_OFF  (AT_OFF + 2 * ATILE)  // 102400: W hi/lo tiles (double buffered)
#define MMA_SMEM_TOTAL (WT_OFF + 2 * 2 * ATILE)  // 176128 bytes

// ---------------- scratch (no allocations allowed) ----------------
__device__ int   g_idx[BATCH * NSENT];
__device__ float g_q  [BATCH * DDIM];
__device__ float g_part[(size_t)KS2 * BATCH * NSENT * DDIM]; // 8 MB fp32 partials
__device__ float g_vpart[(size_t)KS2 * BATCH * NSENT];       // 64 KB v partials
__device__ float g_kf [(size_t)BATCH * NSENT * DDIM];        // 512 KB (RoPE'd K)
__device__ __nv_bfloat16 g_Whi[(size_t)DDIM * HDIM];         // 1 MB
__device__ __nv_bfloat16 g_Wlo[(size_t)DDIM * HDIM];         // 1 MB

// ---------------- PTX helpers (baseline compute_103 only!) ----------------
__device__ __forceinline__ uint32_t smem_u32(const void* p) {
    uint32_t a;
    asm("{ .reg .u64 t; cvta.to.shared.u64 t, %1; cvt.u32.u64 %0, t; }" : "=r"(a) : "l"(p));
    return a;
}
__device__ __forceinline__ void cp_async16(uint32_t saddr, const void* g) {
    asm volatile("cp.async.cg.shared.global [%0], [%1], 16;" :: "r"(saddr), "l"(g));
}
#define CP_COMMIT() asm volatile("cp.async.commit_group;" ::: "memory")
#define CP_WAIT(n)  asm volatile("cp.async.wait_group %0;" :: "n"(n) : "memory")

// ---------------- kernel 0: pre-split Wk into hi/lo bf16 ----------------
__global__ __launch_bounds__(256) void prepw_kernel(const float* __restrict__ Wk) {
    int i = blockIdx.x * 256 + threadIdx.x;       // over DDIM*HDIM/4 = 131072 float4
    if (i >= DDIM * HDIM / 4) return;
    float4 x = ((const float4*)Wk)[i];
    __nv_bfloat162 h0 = __floats2bfloat162_rn(x.x, x.y);
    __nv_bfloat162 h1 = __floats2bfloat162_rn(x.z, x.w);
    __nv_bfloat162 l0 = __floats2bfloat162_rn(x.x - __bfloat162float(h0.x),
                                              x.y - __bfloat162float(h0.y));
    __nv_bfloat162 l1 = __floats2bfloat162_rn(x.z - __bfloat162float(h1.x),
                                              x.w - __bfloat162float(h1.y));
    uint2 hv; hv.x = *(uint32_t*)&h0; hv.y = *(uint32_t*)&h1;
    uint2 lv; lv.x = *(uint32_t*)&l0; lv.y = *(uint32_t*)&l1;
    ((uint2*)g_Whi)[i] = hv;
    ((uint2*)g_Wlo)[i] = lv;
}

// ---------------- kernel 1: extract sentence positions (MLP-64) --------
__global__ void idx_kernel(const int* __restrict__ mask) {
    int b = blockIdx.x;
    int lane = threadIdx.x;            // 32 threads
    const int4* row = (const int4*)(mask + (size_t)b * SEQ);
    int4 v[16];
#pragma unroll
    for (int i = 0; i < 16; i++) v[i] = row[i * 32 + lane];   // all loads in flight
    unsigned lt = (1u << lane) - 1u;
    int count = 0;
#pragma unroll
    for (int i = 0; i < 16; i++) {
        unsigned b0 = __ballot_sync(0xffffffffu, v[i].x != 0);
        unsigned b1 = __ballot_sync(0xffffffffu, v[i].y != 0);
        unsigned b2 = __ballot_sync(0xffffffffu, v[i].z != 0);
        unsigned b3 = __ballot_sync(0xffffffffu, v[i].w != 0);
        int prel = __popc(b0 & lt) + __popc(b1 & lt) + __popc(b2 & lt) + __popc(b3 & lt);
        int basepos = i * 128 + lane * 4;
        int slot = count + prel;
        if (v[i].x) { if (slot < NSENT) g_idx[b * NSENT + slot] = basepos + 0; slot++; }
        if (v[i].y) { if (slot < NSENT) g_idx[b * NSENT + slot] = basepos + 1; slot++; }
        if (v[i].z) { if (slot < NSENT) g_idx[b * NSENT + slot] = basepos + 2; slot++; }
        if (v[i].w) { if (slot < NSENT) g_idx[b * NSENT + slot] = basepos + 3; slot++; }
        count += __popc(b0) + __popc(b1) + __popc(b2) + __popc(b3);
    }
}

// ---------------- kernel 2: q_last GEMV (warp per output d) ----------
__global__ __launch_bounds__(256) void q_kernel(
    const float* __restrict__ hidden,
    const float* __restrict__ Wq, const float* __restrict__ bq)
{
    int warp = threadIdx.x >> 5, lane = threadIdx.x & 31;
    int task = blockIdx.x * 8 + warp;          // 0..1023
    int b = task >> 7, d = task & 127;
    int row = g_idx[b * NSENT + NSENT - 1];
    const float4* x4 = (const float4*)(hidden + ((size_t)b * SEQ + row) * HDIM);
    const float4* w4 = (const float4*)(Wq + (size_t)d * HDIM);
    float s = 0.f;
#pragma unroll 8
    for (int it = 0; it < HDIM / 4 / 32; it++) {
        float4 xa = x4[it * 32 + lane];
        float4 wa = w4[it * 32 + lane];
        s += xa.x * wa.x + xa.y * wa.y + xa.z * wa.z + xa.w * wa.w;
    }
#pragma unroll
    for (int o = 16; o > 0; o >>= 1) s += __shfl_xor_sync(0xffffffffu, s, o);
    if (lane == 0) g_q[task] = s + bq[d];
}

// ---------------- kernel 3: K projection via WMMA bf16 + fused v-GEMV ----
// grid (KS2, BATCH), 256 threads = 8 warps, each warp -> 64x32 output tile.
// smem: 2x raw fp32 A stage | Ahi,Alo tiles | 2x (Whi,Wlo) tiles (from g_W*).
__global__ void __launch_bounds__(256, 1)
mma_kernel(const float* __restrict__ hidden, const float* __restrict__ Wr)
{
    extern __shared__ char smem[];
    __shared__ int idx_sh[NSENT];
    __shared__ float wr_sh[KSL];           // Wr slice for this split (1 KB)

    int t  = threadIdx.x;
    int sp = blockIdx.x, b = blockIdx.y;
    int wid = t >> 5;
    int warp_m = wid >> 2;     // 0..1 -> m base = warp_m*64
    int warp_n = wid & 3;      // 0..3 -> n base = warp_n*32

    const int k0 = sp * KSL;
    if (t < NSENT) idx_sh[t] = g_idx[b * NSENT + t];
    if (t < KSL / 4) ((float4*)wr_sh)[t] = ((const float4*)(Wr + k0))[t];
    __syncthreads();

    __nv_bfloat16* Ahi = (__nv_bfloat16*)(smem + AT_OFF);
    __nv_bfloat16* Alo = (__nv_bfloat16*)(smem + AT_OFF + ATILE);

    wmma::fragment<wmma::accumulator, 16, 16, 16, float> acc[4][2];
#pragma unroll
    for (int i = 0; i < 4; i++)
#pragma unroll
        for (int j = 0; j < 2; j++) wmma::fill_fragment(acc[i][j], 0.0f);

    float vacc = 0.f;          // per-row v partial (threads 0..127)

    // stage issue helper (A raw fp32 + W bf16 tiles direct)
    auto issue_stage = [&](int s) {
        int kk = k0 + s * STG;
        int buf = s & 1;
        float* rawA = (float*)(smem + buf * RAWA_SZ);
        char*  wt   = smem + WT_OFF + buf * 2 * ATILE;
#pragma unroll
        for (int i = 0; i < 8; i++) {             // A: 2048 float4 chunks
            int lin = t + 256 * i, row = lin >> 4, c4 = lin & 15;
            cp_async16(smem_u32(rawA + row * STG + c4 * 4),
                       hidden + ((size_t)b * SEQ + idx_sh[row]) * HDIM + kk + c4 * 4);
        }
#pragma unroll
        for (int i = 0; i < 8; i++) {             // W: 2048 16B chunks (hi then lo)
            int lin = t + 256 * i;
            int mat = lin >> 10;                  // 0=hi, 1=lo
            int rem = lin & 1023;
            int row = rem >> 3, ch = rem & 7;
            const __nv_bfloat16* src = (mat ? g_Wlo : g_Whi) + (size_t)row * HDIM + kk + ch * 8;
            cp_async16(smem_u32(wt + mat * ATILE + row * (TSTRIDE * 2) + ch * 16), src);
        }
        CP_COMMIT();
    };

    issue_stage(0);

    for (int s = 0; s < NSTG; s++) {
        if (s + 1 < NSTG) { issue_stage(s + 1); CP_WAIT(1); }
        else              { CP_WAIT(0); }
        __syncthreads();

        const float4* rawA4 = (const float4*)(smem + (s & 1) * RAWA_SZ);

        // ---- fused v-GEMV partial: thread t<128 dots row t with Wr slice ----
        if (t < 128) {
            const float4* wr4 = (const float4*)(wr_sh + s * STG);
            float a0 = 0.f;
#pragma unroll
            for (int c = 0; c < 16; c++) {
                int cc = (c + t) & 15;             // rotate -> avoid 32-way conflicts
                float4 x = rawA4[t * 16 + cc];
                float4 w = wr4[cc];
                a0 += x.x * w.x + x.y * w.y + x.z * w.z + x.w * w.w;
            }
            vacc += a0;
        }

        // ---- convert raw fp32 A -> hi/lo bf16 tiles ----
#pragma unroll
        for (int i = 0; i < 8; i++) {
            int lin = t + 256 * i, row = lin >> 4, c4 = lin & 15;
            float4 x = rawA4[row * 16 + c4];
            __nv_bfloat162 h0 = __floats2bfloat162_rn(x.x, x.y);
            __nv_bfloat162 h1 = __floats2bfloat162_rn(x.z, x.w);
            __nv_bfloat162 l0 = __floats2bfloat162_rn(x.x - __bfloat162float(h0.x),
                                                      x.y - __bfloat162float(h0.y));
            __nv_bfloat162 l1 = __floats2bfloat162_rn(x.z - __bfloat162float(h1.x),
                                                      x.w - __bfloat162float(h1.y));
            uint2 hv; hv.x = *(uint32_t*)&h0; hv.y = *(uint32_t*)&h1;
            uint2 lv; lv.x = *(uint32_t*)&l0; lv.y = *(uint32_t*)&l1;
            *(uint2*)(Ahi + row * TSTRIDE + c4 * 4) = hv;
            *(uint2*)(Alo + row * TSTRIDE + c4 * 4) = lv;
        }
        __syncthreads();

        // ---- compute: 3 product terms x 4 k16-steps ----
        __nv_bfloat16* Whi = (__nv_bfloat16*)(smem + WT_OFF + (s & 1) * 2 * ATILE);
        __nv_bfloat16* Wlo = (__nv_bfloat16*)((char*)Whi + ATILE);
        const __nv_bfloat16* At[3] = {Ahi, Ahi, Alo};
        const __nv_bfloat16* Bt[3] = {Whi, Wlo, Whi};
#pragma unroll
        for (int term = 0; term < 3; term++) {
            const __nv_bfloat16* Ab = At[term] + warp_m * 64 * TSTRIDE;
            const __nv_bfloat16* Bb = Bt[term] + warp_n * 32 * TSTRIDE;
#pragma unroll
            for (int kk = 0; kk < STG / 16; kk++) {
                wmma::fragment<wmma::matrix_a, 16, 16, 16, __nv_bfloat16, wmma::row_major> af[4];
                wmma::fragment<wmma::matrix_b, 16, 16, 16, __nv_bfloat16, wmma::col_major> bf[2];
#pragma unroll
                for (int i = 0; i < 4; i++)
                    wmma::load_matrix_sync(af[i], Ab + i * 16 * TSTRIDE + kk * 16, TSTRIDE);
#pragma unroll
                for (int j = 0; j < 2; j++)
                    wmma::load_matrix_sync(bf[j], Bb + j * 16 * TSTRIDE + kk * 16, TSTRIDE);
#pragma unroll
                for (int i = 0; i < 4; i++)
#pragma unroll
                    for (int j = 0; j < 2; j++)
                        wmma::mma_sync(acc[i][j], af[i], bf[j], acc[i][j]);
            }
        }
        __syncthreads();   // A tiles + W buf reused next stage
    }

    if (t < 128) g_vpart[(sp * BATCH + b) * NSENT + t] = vacc;

    // ---- epilogue: store split-K partial ----
    float* out = g_part + (((size_t)(sp * BATCH + b)) << 14);
#pragma unroll
    for (int i = 0; i < 4; i++)
#pragma unroll
        for (int j = 0; j < 2; j++)
            wmma::store_matrix_sync(out + (size_t)(warp_m * 64 + i * 16) * DDIM
                                        + warp_n * 32 + j * 16,
                                    acc[i][j], DDIM, wmma::mem_row_major);
}

// ---------------- kernel 4: split-K reduce + bias + RoPE (float2) ----
__global__ __launch_bounds__(256) void kred_kernel(const float* __restrict__ bk) {
    int p = blockIdx.x * 256 + threadIdx.x;       // pair id over B*NS*64 = 65536
    if (p >= BATCH * NSENT * 64) return;
    int b = p >> 13;
    int t = (p >> 6) & 127;                        // sentence index
    int j = p & 63;                                // rotation pair
    int off2 = p & 8191;                           // (t*64 + j)
    float2 s = ((const float2*)bk)[j];
#pragma unroll
    for (int sp = 0; sp < KS2; sp++) {
        float2 v = ((const float2*)g_part)[(((size_t)(sp * BATCH + b)) << 13) + off2];
        s.x += v.x; s.y += v.y;
    }
    // RoPE at position t:  f = theta^(-j/64) = exp2(-j * log2(1e4)/64)
    float f = exp2f(-(float)j * 0.20762050593045163f);
    float ang = (float)t * f;
    float sn, cs; sincosf(ang, &sn, &cs);
    float2 o;
    o.x = s.x * cs - s.y * sn;
    o.y = s.x * sn + s.y * cs;
    ((float2*)g_kf)[p] = o;
}

// ---------------- kernel 5: attention + rewards ----------------------
__global__ __launch_bounds__(128) void finalize_kernel(float* __restrict__ out,
                                                       const float* __restrict__ br) {
    __shared__ float qsh[DDIM];
    __shared__ float red[NSENT];
    __shared__ float vsh[NSENT];
    int b = blockIdx.x, t = threadIdx.x;

    const double LN1E4   = 9.210340371976184;      // ln(10000)
    const double INV_2PI = 0.15915494309189535;
    const double TWO_PI  = 6.283185307179586;

    // reduce v partials (deterministic order) + bias
    {
        float v = br[0];
#pragma unroll
        for (int sp = 0; sp < KS2; sp++)
            v += g_vpart[(sp * BATCH + b) * NSENT + t];
        vsh[t] = v;
    }

    // RoPE q at position NSENT-1, pre-scaled by 1/sqrt(D)
    if (t < DDIM / 2) {
        double f   = exp(-((double)(2 * t) / (double)DDIM) * LN1E4);
        double ang = (double)(NSENT - 1) * f;
        double kk  = rint(ang * INV_2PI);
        float  ar  = (float)(ang - kk * TWO_PI);
        float c, sn; sincosf(ar, &sn, &c);
        float re = g_q[b * DDIM + 2 * t], im = g_q[b * DDIM + 2 * t + 1];
        const float isd = 0.08838834764831845f;    // 1/sqrt(128)
        qsh[2 * t]     = (re * c - im * sn) * isd;
        qsh[2 * t + 1] = (re * sn + im * c) * isd;
    }
    __syncthreads();

    // logit_t = rope(k_t) . rope(q)/sqrt(D)  (k already rotated in kred)
    const float4* krow = (const float4*)(g_kf + ((size_t)b << 14) + (size_t)t * DDIM);
    const float4* q4   = (const float4*)qsh;
    float logit = 0.f;
#pragma unroll
    for (int j = 0; j < DDIM / 4; j++) {
        float4 k4 = krow[j], qq = q4[j];
        logit += k4.x * qq.x + k4.y * qq.y + k4.z * qq.z + k4.w * qq.w;
    }

    // softmax over the 128 sentences
    red[t] = logit; __syncthreads();
#pragma unroll
    for (int o = 64; o > 0; o >>= 1) { if (t < o) red[t] = fmaxf(red[t], red[t + o]); __syncthreads(); }
    float mx = red[0]; __syncthreads();
    float e = expf(logit - mx);
    red[t] = e; __syncthreads();
#pragma unroll
    for (int o = 64; o > 0; o >>= 1) { if (t < o) red[t] += red[t + o]; __syncthreads(); }
    float ssum = red[0]; __syncthreads();
    float attn = e / ssum;

    float v  = vsh[t];
    float sr = (t == 0) ? v : (v - vsh[t - 1]);
    float srw = sr * attn;
    out[b * NSENT + t] = srw;

    red[t] = srw; __syncthreads();
#pragma unroll
    for (int o = 64; o > 0; o >>= 1) { if (t < o) red[t] += red[t + o]; __syncthreads(); }
    if (t == 0) out[BATCH * NSENT + b] = red[0];
}

// ---------------- host launcher ----------------
extern "C" void kernel_launch(void* const* d_in, const int* in_sizes, int n_in,
                              void* d_out, int out_size) {
    const float* hidden = (const float*)d_in[0];
    const int*   mask   = (const int*)d_in[1];
    int off = (n_in > 2 && in_sizes[2] == 1) ? 3 : 2;
    const float* Wq = (const float*)d_in[off + 0];
    const float* bq = (const float*)d_in[off + 1];
    const float* Wk = (const float*)d_in[off + 2];
    const float* bk = (const float*)d_in[off + 3];
    const float* Wr = (const float*)d_in[off + 4];
    const float* br = (const float*)d_in[off + 5];
    float* out = (float*)d_out;

    cudaFuncSetAttribute(mma_kernel, cudaFuncAttributeMaxDynamicSharedMemorySize,
                         MMA_SMEM_TOTAL);

    prepw_kernel<<<DDIM * HDIM / 4 / 256, 256>>>(Wk);
    idx_kernel<<<BATCH, 32>>>(mask);
    mma_kernel<<<dim3(KS2, BATCH), 256, MMA_SMEM_TOTAL>>>(hidden, Wr);
    q_kernel<<<BATCH * DDIM / 8, 256>>>(hidden, Wq, bq);
    kred_kernel<<<(BATCH * NSENT * 64 + 255) / 256, 256>>>(bk);
    finalize_kernel<<<BATCH, 128>>>(out, br);
    (void)in_sizes; (void)n_in; (void)out_size;
}

// round 10
// speedup vs baseline: 1.0213x; 1.0213x over previous
#include <cuda_runtime.h>
#include <cuda_bf16.h>
#include <mma.h>
#include <math.h>
#include <cstdint>

using namespace nvcuda;

// Problem constants (fixed by the dataset)
#define BATCH 8
#define SEQ   2048
#define HDIM  4096
#define DDIM  128
#define NSENT 128

// split-K for the HMMA GEMM
#define KS2   16
#define KSL   (HDIM / KS2)     // 256 fp32 k per CTA
#define STG   64               // k per pipeline stage
#define NSTG  (KSL / STG)      // 4 stages

// split-K for the q GEMV
#define QSPL  8
#define QSEG  (HDIM / QSPL)    // 512 floats per warp segment

#define TSTRIDE 72             // bf16 tile row stride (144B, 16B-aligned, conflict-free)
#define ATILE   (128 * TSTRIDE * 2)   // 18432 bytes per bf16 tile
#define RAWA_SZ (128 * STG * 4)       // 32768 bytes raw fp32 A stage
#define AT_OFF  (2 * RAWA_SZ)         // 65536 : A hi/lo tiles (single buffered)
#define WT_OFF  (AT_OFF + 2 * ATILE)  // 102400: W hi/lo tiles (double buffered)
#define MMA_SMEM_TOTAL (WT_OFF + 2 * 2 * ATILE)  // 176128 bytes

// ---------------- scratch (no allocations allowed) ----------------
__device__ int   g_idx[BATCH * NSENT];
__device__ float g_qpart[QSPL * BATCH * DDIM];               // 32 KB q partials
__device__ float g_part[(size_t)KS2 * BATCH * NSENT * DDIM]; // 8 MB fp32 partials
__device__ float g_vpart[(size_t)KS2 * BATCH * NSENT];       // 64 KB v partials
__device__ float g_kf [(size_t)BATCH * NSENT * DDIM];        // 512 KB (RoPE'd K)
__device__ __nv_bfloat16 g_Whi[(size_t)DDIM * HDIM];         // 1 MB
__device__ __nv_bfloat16 g_Wlo[(size_t)DDIM * HDIM];         // 1 MB

// ---------------- PTX helpers (baseline compute_103 only!) ----------------
__device__ __forceinline__ uint32_t smem_u32(const void* p) {
    uint32_t a;
    asm("{ .reg .u64 t; cvta.to.shared.u64 t, %1; cvt.u32.u64 %0, t; }" : "=r"(a) : "l"(p));
    return a;
}
__device__ __forceinline__ void cp_async16(uint32_t saddr, const void* g) {
    asm volatile("cp.async.cg.shared.global [%0], [%1], 16;" :: "r"(saddr), "l"(g));
}
#define CP_COMMIT() asm volatile("cp.async.commit_group;" ::: "memory")
#define CP_WAIT(n)  asm volatile("cp.async.wait_group %0;" :: "n"(n) : "memory")

// ---------------- kernel 0: pre-split Wk into hi/lo bf16 ----------------
__global__ __launch_bounds__(256) void prepw_kernel(const float* __restrict__ Wk) {
    int i = blockIdx.x * 256 + threadIdx.x;       // over DDIM*HDIM/4 = 131072 float4
    if (i >= DDIM * HDIM / 4) return;
    float4 x = ((const float4*)Wk)[i];
    __nv_bfloat162 h0 = __floats2bfloat162_rn(x.x, x.y);
    __nv_bfloat162 h1 = __floats2bfloat162_rn(x.z, x.w);
    __nv_bfloat162 l0 = __floats2bfloat162_rn(x.x - __bfloat162float(h0.x),
                                              x.y - __bfloat162float(h0.y));
    __nv_bfloat162 l1 = __floats2bfloat162_rn(x.z - __bfloat162float(h1.x),
                                              x.w - __bfloat162float(h1.y));
    uint2 hv; hv.x = *(uint32_t*)&h0; hv.y = *(uint32_t*)&h1;
    uint2 lv; lv.x = *(uint32_t*)&l0; lv.y = *(uint32_t*)&l1;
    ((uint2*)g_Whi)[i] = hv;
    ((uint2*)g_Wlo)[i] = lv;
}

// ---------------- kernel 1: extract sentence positions (MLP-64) --------
__global__ void idx_kernel(const int* __restrict__ mask) {
    int b = blockIdx.x;
    int lane = threadIdx.x;            // 32 threads
    const int4* row = (const int4*)(mask + (size_t)b * SEQ);
    int4 v[16];
#pragma unroll
    for (int i = 0; i < 16; i++) v[i] = row[i * 32 + lane];   // all loads in flight
    unsigned lt = (1u << lane) - 1u;
    int count = 0;
#pragma unroll
    for (int i = 0; i < 16; i++) {
        unsigned b0 = __ballot_sync(0xffffffffu, v[i].x != 0);
        unsigned b1 = __ballot_sync(0xffffffffu, v[i].y != 0);
        unsigned b2 = __ballot_sync(0xffffffffu, v[i].z != 0);
        unsigned b3 = __ballot_sync(0xffffffffu, v[i].w != 0);
        int prel = __popc(b0 & lt) + __popc(b1 & lt) + __popc(b2 & lt) + __popc(b3 & lt);
        int basepos = i * 128 + lane * 4;
        int slot = count + prel;
        if (v[i].x) { if (slot < NSENT) g_idx[b * NSENT + slot] = basepos + 0; slot++; }
        if (v[i].y) { if (slot < NSENT) g_idx[b * NSENT + slot] = basepos + 1; slot++; }
        if (v[i].z) { if (slot < NSENT) g_idx[b * NSENT + slot] = basepos + 2; slot++; }
        if (v[i].w) { if (slot < NSENT) g_idx[b * NSENT + slot] = basepos + 3; slot++; }
        count += __popc(b0) + __popc(b1) + __popc(b2) + __popc(b3);
    }
}

// ---------------- kernel 2: q_last GEMV, split-K x8 (warp per partial) --
// 8192 warps; each warp dots a 512-float segment with all 8 loads batched
// up-front (MLP=8 per thread), writes deterministic partial.
__global__ __launch_bounds__(256) void q_kernel(
    const float* __restrict__ hidden, const float* __restrict__ Wq)
{
    int gw = blockIdx.x * 8 + (threadIdx.x >> 5);   // 0..8191
    int lane = threadIdx.x & 31;
    int sp   = gw & (QSPL - 1);
    int task = gw >> 3;                 // 0..1023
    int b = task >> 7, d = task & 127;
    int row = g_idx[b * NSENT + NSENT - 1];
    const float4* x4 = (const float4*)(hidden + ((size_t)b * SEQ + row) * HDIM + sp * QSEG);
    const float4* w4 = (const float4*)(Wq + (size_t)d * HDIM + sp * QSEG);

    float4 xa[4], wa[4];
#pragma unroll
    for (int it = 0; it < 4; it++) {    // all 8 LDG.128 in flight
        xa[it] = x4[it * 32 + lane];
        wa[it] = w4[it * 32 + lane];
    }
    float s = 0.f;
#pragma unroll
    for (int it = 0; it < 4; it++)
        s += xa[it].x * wa[it].x + xa[it].y * wa[it].y
           + xa[it].z * wa[it].z + xa[it].w * wa[it].w;
#pragma unroll
    for (int o = 16; o > 0; o >>= 1) s += __shfl_xor_sync(0xffffffffu, s, o);
    if (lane == 0) g_qpart[sp * (BATCH * DDIM) + task] = s;
}

// ---------------- kernel 3: K projection via WMMA bf16 + fused v-GEMV ----
// grid (KS2, BATCH), 256 threads = 8 warps, each warp -> 64x32 output tile.
// smem: 2x raw fp32 A stage | Ahi,Alo tiles | 2x (Whi,Wlo) tiles (from g_W*).
__global__ void __launch_bounds__(256, 1)
mma_kernel(const float* __restrict__ hidden, const float* __restrict__ Wr)
{
    extern __shared__ char smem[];
    __shared__ int idx_sh[NSENT];
    __shared__ float wr_sh[KSL];           // Wr slice for this split (1 KB)

    int t  = threadIdx.x;
    int sp = blockIdx.x, b = blockIdx.y;
    int wid = t >> 5;
    int warp_m = wid >> 2;     // 0..1 -> m base = warp_m*64
    int warp_n = wid & 3;      // 0..3 -> n base = warp_n*32

    const int k0 = sp * KSL;
    if (t < NSENT) idx_sh[t] = g_idx[b * NSENT + t];
    if (t < KSL / 4) ((float4*)wr_sh)[t] = ((const float4*)(Wr + k0))[t];
    __syncthreads();

    __nv_bfloat16* Ahi = (__nv_bfloat16*)(smem + AT_OFF);
    __nv_bfloat16* Alo = (__nv_bfloat16*)(smem + AT_OFF + ATILE);

    wmma::fragment<wmma::accumulator, 16, 16, 16, float> acc[4][2];
#pragma unroll
    for (int i = 0; i < 4; i++)
#pragma unroll
        for (int j = 0; j < 2; j++) wmma::fill_fragment(acc[i][j], 0.0f);

    float vacc = 0.f;          // per-row v partial (threads 0..127)

    // stage issue helper (A raw fp32 + W bf16 tiles direct)
    auto issue_stage = [&](int s) {
        int kk = k0 + s * STG;
        int buf = s & 1;
        float* rawA = (float*)(smem + buf * RAWA_SZ);
        char*  wt   = smem + WT_OFF + buf * 2 * ATILE;
#pragma unroll
        for (int i = 0; i < 8; i++) {             // A: 2048 float4 chunks
            int lin = t + 256 * i, row = lin >> 4, c4 = lin & 15;
            cp_async16(smem_u32(rawA + row * STG + c4 * 4),
                       hidden + ((size_t)b * SEQ + idx_sh[row]) * HDIM + kk + c4 * 4);
        }
#pragma unroll
        for (int i = 0; i < 8; i++) {             // W: 2048 16B chunks (hi then lo)
            int lin = t + 256 * i;
            int mat = lin >> 10;                  // 0=hi, 1=lo
            int rem = lin & 1023;
            int row = rem >> 3, ch = rem & 7;
            const __nv_bfloat16* src = (mat ? g_Wlo : g_Whi) + (size_t)row * HDIM + kk + ch * 8;
            cp_async16(smem_u32(wt + mat * ATILE + row * (TSTRIDE * 2) + ch * 16), src);
        }
        CP_COMMIT();
    };

    issue_stage(0);

    for (int s = 0; s < NSTG; s++) {
        if (s + 1 < NSTG) { issue_stage(s + 1); CP_WAIT(1); }
        else              { CP_WAIT(0); }
        __syncthreads();

        const float4* rawA4 = (const float4*)(smem + (s & 1) * RAWA_SZ);

        // ---- fused v-GEMV partial: thread t<128 dots row t with Wr slice ----
        if (t < 128) {
            const float4* wr4 = (const float4*)(wr_sh + s * STG);
            float a0 = 0.f;
#pragma unroll
            for (int c = 0; c < 16; c++) {
                int cc = (c + t) & 15;             // rotate -> avoid 32-way conflicts
                float4 x = rawA4[t * 16 + cc];
                float4 w = wr4[cc];
                a0 += x.x * w.x + x.y * w.y + x.z * w.z + x.w * w.w;
            }
            vacc += a0;
        }

        // ---- convert raw fp32 A -> hi/lo bf16 tiles ----
#pragma unroll
        for (int i = 0; i < 8; i++) {
            int lin = t + 256 * i, row = lin >> 4, c4 = lin & 15;
            float4 x = rawA4[row * 16 + c4];
            __nv_bfloat162 h0 = __floats2bfloat162_rn(x.x, x.y);
            __nv_bfloat162 h1 = __floats2bfloat162_rn(x.z, x.w);
            __nv_bfloat162 l0 = __floats2bfloat162_rn(x.x - __bfloat162float(h0.x),
                                                      x.y - __bfloat162float(h0.y));
            __nv_bfloat162 l1 = __floats2bfloat162_rn(x.z - __bfloat162float(h1.x),
                                                      x.w - __bfloat162float(h1.y));
            uint2 hv; hv.x = *(uint32_t*)&h0; hv.y = *(uint32_t*)&h1;
            uint2 lv; lv.x = *(uint32_t*)&l0; lv.y = *(uint32_t*)&l1;
            *(uint2*)(Ahi + row * TSTRIDE + c4 * 4) = hv;
            *(uint2*)(Alo + row * TSTRIDE + c4 * 4) = lv;
        }
        __syncthreads();

        // ---- compute: 3 product terms x 4 k16-steps ----
        __nv_bfloat16* Whi = (__nv_bfloat16*)(smem + WT_OFF + (s & 1) * 2 * ATILE);
        __nv_bfloat16* Wlo = (__nv_bfloat16*)((char*)Whi + ATILE);
        const __nv_bfloat16* At[3] = {Ahi, Ahi, Alo};
        const __nv_bfloat16* Bt[3] = {Whi, Wlo, Whi};
#pragma unroll
        for (int term = 0; term < 3; term++) {
            const __nv_bfloat16* Ab = At[term] + warp_m * 64 * TSTRIDE;
            const __nv_bfloat16* Bb = Bt[term] + warp_n * 32 * TSTRIDE;
#pragma unroll
            for (int kk = 0; kk < STG / 16; kk++) {
                wmma::fragment<wmma::matrix_a, 16, 16, 16, __nv_bfloat16, wmma::row_major> af[4];
                wmma::fragment<wmma::matrix_b, 16, 16, 16, __nv_bfloat16, wmma::col_major> bf[2];
#pragma unroll
                for (int i = 0; i < 4; i++)
                    wmma::load_matrix_sync(af[i], Ab + i * 16 * TSTRIDE + kk * 16, TSTRIDE);
#pragma unroll
                for (int j = 0; j < 2; j++)
                    wmma::load_matrix_sync(bf[j], Bb + j * 16 * TSTRIDE + kk * 16, TSTRIDE);
#pragma unroll
                for (int i = 0; i < 4; i++)
#pragma unroll
                    for (int j = 0; j < 2; j++)
                        wmma::mma_sync(acc[i][j], af[i], bf[j], acc[i][j]);
            }
        }
        __syncthreads();   // A tiles + W buf reused next stage
    }

    if (t < 128) g_vpart[(sp * BATCH + b) * NSENT + t] = vacc;

    // ---- epilogue: store split-K partial ----
    float* out = g_part + (((size_t)(sp * BATCH + b)) << 14);
#pragma unroll
    for (int i = 0; i < 4; i++)
#pragma unroll
        for (int j = 0; j < 2; j++)
            wmma::store_matrix_sync(out + (size_t)(warp_m * 64 + i * 16) * DDIM
                                        + warp_n * 32 + j * 16,
                                    acc[i][j], DDIM, wmma::mem_row_major);
}

// ---------------- kernel 4: split-K reduce + bias + RoPE (float2) ----
__global__ __launch_bounds__(256) void kred_kernel(const float* __restrict__ bk) {
    int p = blockIdx.x * 256 + threadIdx.x;       // pair id over B*NS*64 = 65536
    if (p >= BATCH * NSENT * 64) return;
    int b = p >> 13;
    int t = (p >> 6) & 127;                        // sentence index
    int j = p & 63;                                // rotation pair
    int off2 = p & 8191;                           // (t*64 + j)
    float2 s = ((const float2*)bk)[j];
#pragma unroll
    for (int sp = 0; sp < KS2; sp++) {
        float2 v = ((const float2*)g_part)[(((size_t)(sp * BATCH + b)) << 13) + off2];
        s.x += v.x; s.y += v.y;
    }
    // RoPE at position t:  f = theta^(-j/64) = exp2(-j * log2(1e4)/64)
    float f = exp2f(-(float)j * 0.20762050593045163f);
    float ang = (float)t * f;
    float sn, cs; sincosf(ang, &sn, &cs);
    float2 o;
    o.x = s.x * cs - s.y * sn;
    o.y = s.x * sn + s.y * cs;
    ((float2*)g_kf)[p] = o;
}

// ---------------- kernel 5: attention + rewards ----------------------
__global__ __launch_bounds__(128) void finalize_kernel(float* __restrict__ out,
                                                       const float* __restrict__ bq,
                                                       const float* __restrict__ br) {
    __shared__ float qfull[DDIM];
    __shared__ float qsh[DDIM];
    __shared__ float red[NSENT];
    __shared__ float vsh[NSENT];
    int b = blockIdx.x, t = threadIdx.x;

    const double LN1E4   = 9.210340371976184;      // ln(10000)
    const double INV_2PI = 0.15915494309189535;
    const double TWO_PI  = 6.283185307179586;

    // reduce v partials (deterministic order) + bias
    {
        float v = br[0];
#pragma unroll
        for (int sp = 0; sp < KS2; sp++)
            v += g_vpart[(sp * BATCH + b) * NSENT + t];
        vsh[t] = v;
    }
    // reduce q partials (deterministic order) + bias
    {
        float qv = bq[t];
#pragma unroll
        for (int sp = 0; sp < QSPL; sp++)
            qv += g_qpart[sp * (BATCH * DDIM) + b * DDIM + t];
        qfull[t] = qv;
    }
    __syncthreads();

    // RoPE q at position NSENT-1, pre-scaled by 1/sqrt(D)
    if (t < DDIM / 2) {
        double f   = exp(-((double)(2 * t) / (double)DDIM) * LN1E4);
        double ang = (double)(NSENT - 1) * f;
        double kk  = rint(ang * INV_2PI);
        float  ar  = (float)(ang - kk * TWO_PI);
        float c, sn; sincosf(ar, &sn, &c);
        float re = qfull[2 * t], im = qfull[2 * t + 1];
        const float isd = 0.08838834764831845f;    // 1/sqrt(128)
        qsh[2 * t]     = (re * c - im * sn) * isd;
        qsh[2 * t + 1] = (re * sn + im * c) * isd;
    }
    __syncthreads();

    // logit_t = rope(k_t) . rope(q)/sqrt(D)  (k already rotated in kred)
    const float4* krow = (const float4*)(g_kf + ((size_t)b << 14) + (size_t)t * DDIM);
    const float4* q4   = (const float4*)qsh;
    float logit = 0.f;
#pragma unroll
    for (int j = 0; j < DDIM / 4; j++) {
        float4 k4 = krow[j], qq = q4[j];
        logit += k4.x * qq.x + k4.y * qq.y + k4.z * qq.z + k4.w * qq.w;
    }

    // softmax over the 128 sentences
    red[t] = logit; __syncthreads();
#pragma unroll
    for (int o = 64; o > 0; o >>= 1) { if (t < o) red[t] = fmaxf(red[t], red[t + o]); __syncthreads(); }
    float mx = red[0]; __syncthreads();
    float e = expf(logit - mx);
    red[t] = e; __syncthreads();
#pragma unroll
    for (int o = 64; o > 0; o >>= 1) { if (t < o) red[t] += red[t + o]; __syncthreads(); }
    float ssum = red[0]; __syncthreads();
    float attn = e / ssum;

    float v  = vsh[t];
    float sr = (t == 0) ? v : (v - vsh[t - 1]);
    float srw = sr * attn;
    out[b * NSENT + t] = srw;

    red[t] = srw; __syncthreads();
#pragma unroll
    for (int o = 64; o > 0; o >>= 1) { if (t < o) red[t] += red[t + o]; __syncthreads(); }
    if (t == 0) out[BATCH * NSENT + b] = red[0];
}

// ---------------- host launcher ----------------
extern "C" void kernel_launch(void* const* d_in, const int* in_sizes, int n_in,
                              void* d_out, int out_size) {
    const float* hidden = (const float*)d_in[0];
    const int*   mask   = (const int*)d_in[1];
    int off = (n_in > 2 && in_sizes[2] == 1) ? 3 : 2;
    const float* Wq = (const float*)d_in[off + 0];
    const float* bq = (const float*)d_in[off + 1];
    const float* Wk = (const float*)d_in[off + 2];
    const float* bk = (const float*)d_in[off + 3];
    const float* Wr = (const float*)d_in[off + 4];
    const float* br = (const float*)d_in[off + 5];
    float* out = (float*)d_out;

    cudaFuncSetAttribute(mma_kernel, cudaFuncAttributeMaxDynamicSharedMemorySize,
                         MMA_SMEM_TOTAL);

    prepw_kernel<<<DDIM * HDIM / 4 / 256, 256>>>(Wk);
    idx_kernel<<<BATCH, 32>>>(mask);
    q_kernel<<<QSPL * BATCH * DDIM / 8, 256>>>(hidden, Wq);
    mma_kernel<<<dim3(KS2, BATCH), 256, MMA_SMEM_TOTAL>>>(hidden, Wr);
    kred_kernel<<<(BATCH * NSENT * 64 + 255) / 256, 256>>>(bk);
    finalize_kernel<<<BATCH, 128>>>(out, bq, br);
    (void)in_sizes; (void)n_in; (void)out_size;
}

// round 11
// speedup vs baseline: 1.0528x; 1.0309x over previous
#include <cuda_runtime.h>
#include <cuda_bf16.h>
#include <mma.h>
#include <math.h>
#include <cstdint>

using namespace nvcuda;

// Problem constants (fixed by the dataset)
#define BATCH 8
#define SEQ   2048
#define HDIM  4096
#define DDIM  128
#define NSENT 128

// split-K for the HMMA GEMM
#define KS2   16
#define KSL   (HDIM / KS2)     // 256 fp32 k per CTA
#define STG   64               // k per pipeline stage
#define NSTG  (KSL / STG)      // 4 stages

// split-K for the q/v GEMVs
#define QSPL  8
#define QSEG  (HDIM / QSPL)    // 512 floats per warp segment

#define TSTRIDE 72                    // bf16 tile row stride (144B)
#define ATILE   (128 * TSTRIDE * 2)   // 18432 bytes per bf16 tile
#define ASTAGE  (2 * ATILE)           // hi+lo = 36864
#define RAWA_SZ (128 * STG * 4)       // 32768 bytes raw fp32 A stage
#define AT_OFF  (2 * RAWA_SZ)         // 65536
#define WT_OFF  (AT_OFF + 2 * ASTAGE) // 139264
#define MMA_SMEM_TOTAL (WT_OFF + 2 * ASTAGE)   // 212992 bytes

// ---------------- scratch (no allocations allowed) ----------------
__device__ int   g_idx[BATCH * NSENT];
__device__ float g_qpart[QSPL * BATCH * DDIM];               // 32 KB
__device__ float g_vpart[QSPL * BATCH * NSENT];              // 32 KB
__device__ float g_part[(size_t)KS2 * BATCH * NSENT * DDIM]; // 8 MB fp32 partials
__device__ float g_kf [(size_t)BATCH * NSENT * DDIM];        // 512 KB (RoPE'd K)
__device__ __nv_bfloat16 g_Whi[(size_t)DDIM * HDIM];         // 1 MB
__device__ __nv_bfloat16 g_Wlo[(size_t)DDIM * HDIM];         // 1 MB

// ---------------- PTX helpers (baseline compute_103 only!) ----------------
__device__ __forceinline__ uint32_t smem_u32(const void* p) {
    uint32_t a;
    asm("{ .reg .u64 t; cvta.to.shared.u64 t, %1; cvt.u32.u64 %0, t; }" : "=r"(a) : "l"(p));
    return a;
}
__device__ __forceinline__ void cp_async16(uint32_t saddr, const void* g) {
    asm volatile("cp.async.cg.shared.global [%0], [%1], 16;" :: "r"(saddr), "l"(g));
}
#define CP_COMMIT() asm volatile("cp.async.commit_group;" ::: "memory")
#define CP_WAIT(n)  asm volatile("cp.async.wait_group %0;" :: "n"(n) : "memory")

// ---------------- kernel 0: pre-split Wk into hi/lo bf16 ----------------
__global__ __launch_bounds__(256) void prepw_kernel(const float* __restrict__ Wk) {
    int i = blockIdx.x * 256 + threadIdx.x;       // over DDIM*HDIM/4 = 131072 float4
    if (i >= DDIM * HDIM / 4) return;
    float4 x = ((const float4*)Wk)[i];
    __nv_bfloat162 h0 = __floats2bfloat162_rn(x.x, x.y);
    __nv_bfloat162 h1 = __floats2bfloat162_rn(x.z, x.w);
    __nv_bfloat162 l0 = __floats2bfloat162_rn(x.x - __bfloat162float(h0.x),
                                              x.y - __bfloat162float(h0.y));
    __nv_bfloat162 l1 = __floats2bfloat162_rn(x.z - __bfloat162float(h1.x),
                                              x.w - __bfloat162float(h1.y));
    uint2 hv; hv.x = *(uint32_t*)&h0; hv.y = *(uint32_t*)&h1;
    uint2 lv; lv.x = *(uint32_t*)&l0; lv.y = *(uint32_t*)&l1;
    ((uint2*)g_Whi)[i] = hv;
    ((uint2*)g_Wlo)[i] = lv;
}

// ---------------- kernel 1: extract sentence positions (MLP-64) --------
__global__ void idx_kernel(const int* __restrict__ mask) {
    int b = blockIdx.x;
    int lane = threadIdx.x;            // 32 threads
    const int4* row = (const int4*)(mask + (size_t)b * SEQ);
    int4 v[16];
#pragma unroll
    for (int i = 0; i < 16; i++) v[i] = row[i * 32 + lane];   // all loads in flight
    unsigned lt = (1u << lane) - 1u;
    int count = 0;
#pragma unroll
    for (int i = 0; i < 16; i++) {
        unsigned b0 = __ballot_sync(0xffffffffu, v[i].x != 0);
        unsigned b1 = __ballot_sync(0xffffffffu, v[i].y != 0);
        unsigned b2 = __ballot_sync(0xffffffffu, v[i].z != 0);
        unsigned b3 = __ballot_sync(0xffffffffu, v[i].w != 0);
        int prel = __popc(b0 & lt) + __popc(b1 & lt) + __popc(b2 & lt) + __popc(b3 & lt);
        int basepos = i * 128 + lane * 4;
        int slot = count + prel;
        if (v[i].x) { if (slot < NSENT) g_idx[b * NSENT + slot] = basepos + 0; slot++; }
        if (v[i].y) { if (slot < NSENT) g_idx[b * NSENT + slot] = basepos + 1; slot++; }
        if (v[i].z) { if (slot < NSENT) g_idx[b * NSENT + slot] = basepos + 2; slot++; }
        if (v[i].w) { if (slot < NSENT) g_idx[b * NSENT + slot] = basepos + 3; slot++; }
        count += __popc(b0) + __popc(b1) + __popc(b2) + __popc(b3);
    }
}

// ---------------- kernel 2: q + v GEMVs, split-K x8 (warp per partial) --
// 16384 warps; each dots a 512-float segment with all 8 LDG.128 batched.
__global__ __launch_bounds__(256) void qv_kernel(
    const float* __restrict__ hidden,
    const float* __restrict__ Wq, const float* __restrict__ Wr)
{
    int gw = blockIdx.x * 8 + (threadIdx.x >> 5);   // 0..16383
    int lane = threadIdx.x & 31;
    int sp   = gw & (QSPL - 1);
    int task = gw >> 3;                 // 0..2047
    const float4* x4;
    const float4* w4;
    if (task < BATCH * DDIM) {          // q task
        int b = task >> 7, d = task & 127;
        int row = g_idx[b * NSENT + NSENT - 1];
        x4 = (const float4*)(hidden + ((size_t)b * SEQ + row) * HDIM + sp * QSEG);
        w4 = (const float4*)(Wq + (size_t)d * HDIM + sp * QSEG);
    } else {                            // v task
        int tt = task - BATCH * DDIM;
        int b = tt >> 7, i = tt & 127;
        int row = g_idx[b * NSENT + i];
        x4 = (const float4*)(hidden + ((size_t)b * SEQ + row) * HDIM + sp * QSEG);
        w4 = (const float4*)(Wr + sp * QSEG);
    }
    float4 xa[4], wa[4];
#pragma unroll
    for (int it = 0; it < 4; it++) {    // all 8 LDG.128 in flight
        xa[it] = x4[it * 32 + lane];
        wa[it] = w4[it * 32 + lane];
    }
    float s = 0.f;
#pragma unroll
    for (int it = 0; it < 4; it++)
        s += xa[it].x * wa[it].x + xa[it].y * wa[it].y
           + xa[it].z * wa[it].z + xa[it].w * wa[it].w;
#pragma unroll
    for (int o = 16; o > 0; o >>= 1) s += __shfl_xor_sync(0xffffffffu, s, o);
    if (lane == 0) {
        if (task < BATCH * DDIM) g_qpart[sp * (BATCH * DDIM) + task] = s;
        else g_vpart[sp * (BATCH * NSENT) + task - BATCH * DDIM] = s;
    }
}

// ---------------- kernel 3: K projection via WMMA bf16 (3-term split) ----
// grid (KS2, BATCH), 256 threads = 8 warps, each warp -> 64x32 output tile.
// Pipeline: A raw issued 2 stages ahead; W tiles issued post-barrier;
// fp32->bf16 convert of stage s+1 interleaved with HMMAs of stage s.
__global__ void __launch_bounds__(256, 1)
mma_kernel(const float* __restrict__ hidden)
{
    extern __shared__ char smem[];
    __shared__ int idx_sh[NSENT];

    int t  = threadIdx.x;
    int sp = blockIdx.x, b = blockIdx.y;
    int wid = t >> 5;
    int warp_m = wid >> 2;     // 0..1 -> m base = warp_m*64
    int warp_n = wid & 3;      // 0..3 -> n base = warp_n*32

    const int k0 = sp * KSL;
    if (t < NSENT) idx_sh[t] = g_idx[b * NSENT + t];
    __syncthreads();

    wmma::fragment<wmma::accumulator, 16, 16, 16, float> acc[4][2];
#pragma unroll
    for (int i = 0; i < 4; i++)
#pragma unroll
        for (int j = 0; j < 2; j++) wmma::fill_fragment(acc[i][j], 0.0f);

    auto issueA = [&](int s) {
        int kk = k0 + s * STG;
        float* rawA = (float*)(smem + (s & 1) * RAWA_SZ);
#pragma unroll
        for (int i = 0; i < 8; i++) {
            int lin = t + 256 * i, row = lin >> 4, c4 = lin & 15;
            cp_async16(smem_u32(rawA + row * STG + c4 * 4),
                       hidden + ((size_t)b * SEQ + idx_sh[row]) * HDIM + kk + c4 * 4);
        }
        CP_COMMIT();
    };
    auto issueW = [&](int s) {
        int kk = k0 + s * STG;
        char* wt = smem + WT_OFF + (s & 1) * ASTAGE;
#pragma unroll
        for (int i = 0; i < 8; i++) {             // 2048 16B chunks (hi then lo)
            int lin = t + 256 * i;
            int mat = lin >> 10;                  // 0=hi, 1=lo
            int rem = lin & 1023;
            int row = rem >> 3, ch = rem & 7;
            const __nv_bfloat16* src = (mat ? g_Wlo : g_Whi) + (size_t)row * HDIM + kk + ch * 8;
            cp_async16(smem_u32(wt + mat * ATILE + row * (TSTRIDE * 2) + ch * 16), src);
        }
        CP_COMMIT();
    };
    // convert 2 of the 8 chunks of stage s's raw A into bf16 hi/lo tiles
    auto convert2 = [&](int s, int i0) {
        const float4* rawA4 = (const float4*)(smem + (s & 1) * RAWA_SZ);
        __nv_bfloat16* Ahi = (__nv_bfloat16*)(smem + AT_OFF + (s & 1) * ASTAGE);
        __nv_bfloat16* Alo = (__nv_bfloat16*)((char*)Ahi + ATILE);
#pragma unroll
        for (int i = i0; i < i0 + 2; i++) {
            int lin = t + 256 * i, row = lin >> 4, c4 = lin & 15;
            float4 x = rawA4[row * 16 + c4];
            __nv_bfloat162 h0 = __floats2bfloat162_rn(x.x, x.y);
            __nv_bfloat162 h1 = __floats2bfloat162_rn(x.z, x.w);
            __nv_bfloat162 l0 = __floats2bfloat162_rn(x.x - __bfloat162float(h0.x),
                                                      x.y - __bfloat162float(h0.y));
            __nv_bfloat162 l1 = __floats2bfloat162_rn(x.z - __bfloat162float(h1.x),
                                                      x.w - __bfloat162float(h1.y));
            uint2 hv; hv.x = *(uint32_t*)&h0; hv.y = *(uint32_t*)&h1;
            uint2 lv; lv.x = *(uint32_t*)&l0; lv.y = *(uint32_t*)&l1;
            *(uint2*)(Ahi + row * TSTRIDE + c4 * 4) = hv;
            *(uint2*)(Alo + row * TSTRIDE + c4 * 4) = lv;
        }
    };

    // prologue: stages 0 and 1 in flight (groups: A0, W0, A1, W1)
    issueA(0); issueW(0); issueA(1); issueW(1);
    CP_WAIT(2);                 // A0, W0 done
    __syncthreads();
    convert2(0, 0); convert2(0, 2); convert2(0, 4); convert2(0, 6);
    __syncthreads();

    for (int s = 0; s < NSTG; s++) {
        if (s + 2 < NSTG) { issueA(s + 2); CP_WAIT(1); }   // leaves only A(s+2) pending
        else              { CP_WAIT(0); }
        // raw(s+1) + W tiles(s+1) are now resident

        const __nv_bfloat16* Ah = (const __nv_bfloat16*)(smem + AT_OFF + (s & 1) * ASTAGE);
        const __nv_bfloat16* Al = (const __nv_bfloat16*)((char*)Ah + ATILE);
        const __nv_bfloat16* Wh = (const __nv_bfloat16*)(smem + WT_OFF + (s & 1) * ASTAGE);
        const __nv_bfloat16* Wl = (const __nv_bfloat16*)((char*)Wh + ATILE);
        const __nv_bfloat16* Ab = Ah + warp_m * 64 * TSTRIDE;
        const __nv_bfloat16* Lb = Al + warp_m * 64 * TSTRIDE;
        const __nv_bfloat16* WhB = Wh + warp_n * 32 * TSTRIDE;
        const __nv_bfloat16* WlB = Wl + warp_n * 32 * TSTRIDE;

#pragma unroll
        for (int kk = 0; kk < STG / 16; kk++) {
            wmma::fragment<wmma::matrix_a, 16, 16, 16, __nv_bfloat16, wmma::row_major> ah[4], al[4];
            wmma::fragment<wmma::matrix_b, 16, 16, 16, __nv_bfloat16, wmma::col_major> wh[2], wl[2];
#pragma unroll
            for (int i = 0; i < 4; i++) {
                wmma::load_matrix_sync(ah[i], Ab + i * 16 * TSTRIDE + kk * 16, TSTRIDE);
                wmma::load_matrix_sync(al[i], Lb + i * 16 * TSTRIDE + kk * 16, TSTRIDE);
            }
#pragma unroll
            for (int j = 0; j < 2; j++) {
                wmma::load_matrix_sync(wh[j], WhB + j * 16 * TSTRIDE + kk * 16, TSTRIDE);
                wmma::load_matrix_sync(wl[j], WlB + j * 16 * TSTRIDE + kk * 16, TSTRIDE);
            }
#pragma unroll
            for (int i = 0; i < 4; i++)
#pragma unroll
                for (int j = 0; j < 2; j++) {
                    wmma::mma_sync(acc[i][j], ah[i], wh[j], acc[i][j]);
                    wmma::mma_sync(acc[i][j], ah[i], wl[j], acc[i][j]);
                    wmma::mma_sync(acc[i][j], al[i], wh[j], acc[i][j]);
                }
            if (s + 1 < NSTG) convert2(s + 1, 2 * kk);   // overlap convert with HMMA drain
        }
        __syncthreads();                  // tiles(s+1) complete; W buf (s&1) free
        if (s + 2 < NSTG) issueW(s + 2);  // safe: nobody reads W[(s)&1] anymore
    }

    // ---- epilogue: store split-K partial ----
    float* out = g_part + (((size_t)(sp * BATCH + b)) << 14);
#pragma unroll
    for (int i = 0; i < 4; i++)
#pragma unroll
        for (int j = 0; j < 2; j++)
            wmma::store_matrix_sync(out + (size_t)(warp_m * 64 + i * 16) * DDIM
                                        + warp_n * 32 + j * 16,
                                    acc[i][j], DDIM, wmma::mem_row_major);
}

// ---------------- kernel 4: split-K reduce + bias + RoPE (float2) ----
__global__ __launch_bounds__(256) void kred_kernel(const float* __restrict__ bk) {
    int p = blockIdx.x * 256 + threadIdx.x;       // pair id over B*NS*64 = 65536
    if (p >= BATCH * NSENT * 64) return;
    int b = p >> 13;
    int t = (p >> 6) & 127;                        // sentence index
    int j = p & 63;                                // rotation pair
    int off2 = p & 8191;                           // (t*64 + j)
    float2 s = ((const float2*)bk)[j];
#pragma unroll
    for (int sp = 0; sp < KS2; sp++) {
        float2 v = ((const float2*)g_part)[(((size_t)(sp * BATCH + b)) << 13) + off2];
        s.x += v.x; s.y += v.y;
    }
    // RoPE at position t:  f = theta^(-j/64) = exp2(-j * log2(1e4)/64)
    float f = exp2f(-(float)j * 0.20762050593045163f);
    float ang = (float)t * f;
    float sn, cs; sincosf(ang, &sn, &cs);
    float2 o;
    o.x = s.x * cs - s.y * sn;
    o.y = s.x * sn + s.y * cs;
    ((float2*)g_kf)[p] = o;
}

// ---------------- kernel 5: attention + rewards ----------------------
__global__ __launch_bounds__(128) void finalize_kernel(float* __restrict__ out,
                                                       const float* __restrict__ bq,
                                                       const float* __restrict__ br) {
    __shared__ float qfull[DDIM];
    __shared__ float qsh[DDIM];
    __shared__ float red[NSENT];
    __shared__ float vsh[NSENT];
    int b = blockIdx.x, t = threadIdx.x;

    const double LN1E4   = 9.210340371976184;      // ln(10000)
    const double INV_2PI = 0.15915494309189535;
    const double TWO_PI  = 6.283185307179586;

    // reduce v partials (deterministic order) + bias
    {
        float v = br[0];
#pragma unroll
        for (int sp = 0; sp < QSPL; sp++)
            v += g_vpart[sp * (BATCH * NSENT) + b * NSENT + t];
        vsh[t] = v;
    }
    // reduce q partials (deterministic order) + bias
    {
        float qv = bq[t];
#pragma unroll
        for (int sp = 0; sp < QSPL; sp++)
            qv += g_qpart[sp * (BATCH * DDIM) + b * DDIM + t];
        qfull[t] = qv;
    }
    __syncthreads();

    // RoPE q at position NSENT-1, pre-scaled by 1/sqrt(D)
    if (t < DDIM / 2) {
        double f   = exp(-((double)(2 * t) / (double)DDIM) * LN1E4);
        double ang = (double)(NSENT - 1) * f;
        double kk  = rint(ang * INV_2PI);
        float  ar  = (float)(ang - kk * TWO_PI);
        float c, sn; sincosf(ar, &sn, &c);
        float re = qfull[2 * t], im = qfull[2 * t + 1];
        const float isd = 0.08838834764831845f;    // 1/sqrt(128)
        qsh[2 * t]     = (re * c - im * sn) * isd;
        qsh[2 * t + 1] = (re * sn + im * c) * isd;
    }
    __syncthreads();

    // logit_t = rope(k_t) . rope(q)/sqrt(D)  (k already rotated in kred)
    const float4* krow = (const float4*)(g_kf + ((size_t)b << 14) + (size_t)t * DDIM);
    const float4* q4   = (const float4*)qsh;
    float logit = 0.f;
#pragma unroll
    for (int j = 0; j < DDIM / 4; j++) {
        float4 k4 = krow[j], qq = q4[j];
        logit += k4.x * qq.x + k4.y * qq.y + k4.z * qq.z + k4.w * qq.w;
    }

    // softmax over the 128 sentences
    red[t] = logit; __syncthreads();
#pragma unroll
    for (int o = 64; o > 0; o >>= 1) { if (t < o) red[t] = fmaxf(red[t], red[t + o]); __syncthreads(); }
    float mx = red[0]; __syncthreads();
    float e = expf(logit - mx);
    red[t] = e; __syncthreads();
#pragma unroll
    for (int o = 64; o > 0; o >>= 1) { if (t < o) red[t] += red[t + o]; __syncthreads(); }
    float ssum = red[0]; __syncthreads();
    float attn = e / ssum;

    float v  = vsh[t];
    float sr = (t == 0) ? v : (v - vsh[t - 1]);
    float srw = sr * attn;
    out[b * NSENT + t] = srw;

    red[t] = srw; __syncthreads();
#pragma unroll
    for (int o = 64; o > 0; o >>= 1) { if (t < o) red[t] += red[t + o]; __syncthreads(); }
    if (t == 0) out[BATCH * NSENT + b] = red[0];
}

// ---------------- host launcher ----------------
extern "C" void kernel_launch(void* const* d_in, const int* in_sizes, int n_in,
                              void* d_out, int out_size) {
    const float* hidden = (const float*)d_in[0];
    const int*   mask   = (const int*)d_in[1];
    int off = (n_in > 2 && in_sizes[2] == 1) ? 3 : 2;
    const float* Wq = (const float*)d_in[off + 0];
    const float* bq = (const float*)d_in[off + 1];
    const float* Wk = (const float*)d_in[off + 2];
    const float* bk = (const float*)d_in[off + 3];
    const float* Wr = (const float*)d_in[off + 4];
    const float* br = (const float*)d_in[off + 5];
    float* out = (float*)d_out;

    cudaFuncSetAttribute(mma_kernel, cudaFuncAttributeMaxDynamicSharedMemorySize,
                         MMA_SMEM_TOTAL);

    prepw_kernel<<<DDIM * HDIM / 4 / 256, 256>>>(Wk);
    idx_kernel<<<BATCH, 32>>>(mask);
    qv_kernel<<<QSPL * 2 * BATCH * NSENT / 8, 256>>>(hidden, Wq, Wr);
    mma_kernel<<<dim3(KS2, BATCH), 256, MMA_SMEM_TOTAL>>>(hidden);
    kred_kernel<<<(BATCH * NSENT * 64 + 255) / 256, 256>>>(bk);
    finalize_kernel<<<BATCH, 128>>>(out, bq, br);
    (void)in_sizes; (void)n_in; (void)out_size;
}